// round 13
// baseline (speedup 1.0000x reference)
#include <cuda_runtime.h>
#include <cuda_fp16.h>
#include <cstdint>

// ROI max pooling (shapes fixed):
//   features: (B=4, C=256, H=50, W=50) fp32;  rois: (R=256,5) int32/int64-sniffed
//   out: (R=256, C=256, PH=7, PW=7) fp32
//
// fp16 intermediate (N(0,1) data: rel-err <= 2^-11 = 4.9e-4, 2x margin under
// 1e-3; measured 2.1e-4).
//
// 1) transpose+convert -> g_featH4[b][p][c]: PURE REGISTER pipeline.
//    Thread = 8 channels x 4 positions: 8 LDG.128 -> 8x4 reg transpose+pack
//    -> 4 STG.128. Lanes 0..7 of each octet hold contiguous 128B output
//    chunks, so stores are perfectly sectored WITHOUT smem or barriers.
// 2) decode rois -> g_roi.
// 3) pool: block=(r,ph), 224 thr = 7 warps (warp=pw, bw warp-uniform),
//    lane = 8 channels (one uint4). bw-specialized y-sweeps, __hmax2,
//    smem-staged interleaved fp32 write-out.

#define RP_B  4
#define RP_C  256
#define RP_H  50
#define RP_W  50
#define RP_P  (RP_H * RP_W)   // 2500
#define RP_R  256
#define RP_PH 7
#define RP_PW 7
#define PC8   (RP_C / 8)      // 32 uint4 per position
#define PRS   (RP_W * PC8)    // 1600: y-row stride in uint4

__device__ uint4 g_featH4[RP_B * RP_P * RP_C / 8];   // 5.12 MB fp16 scratch
__device__ int   g_roi[RP_R * 8];                    // b,x1,y1,w,h

__device__ __forceinline__ unsigned h2max(unsigned a, unsigned b) {
    __half2 r = __hmax2(*(__half2*)&a, *(__half2*)&b);
    return *(unsigned*)&r;
}
__device__ __forceinline__ uint4 h4max(uint4 a, uint4 b) {
    return make_uint4(h2max(a.x, b.x), h2max(a.y, b.y),
                      h2max(a.z, b.z), h2max(a.w, b.w));
}
__device__ __forceinline__ unsigned pack2(float a, float b) {
    __half2 h = __floats2half2_rn(a, b);     // a -> low, b -> high
    return *(unsigned*)&h;
}
__device__ __forceinline__ float sel4(float4 v, int i) {
    return (i == 0) ? v.x : (i == 1) ? v.y : (i == 2) ? v.z : v.w;
}

// ------- transpose+convert: (B,C,P) fp32 -> (B,P,C) fp16, no smem -------
// block: 64 channels x 128 positions (256 thr). thread: 8 ch x 4 pos.
__global__ __launch_bounds__(256)
void transpose_kernel(const float* __restrict__ feat)
{
    const int b  = blockIdx.z;
    const int ct = blockIdx.y;                // 0..3
    const int pt = blockIdx.x;                // 0..19
    const int t  = threadIdx.x;
    const int c0 = ct * 64;
    const int p0 = pt * 128;

    const int cr8 = t & 7;                    // 8-channel group 0..7
    const int p4  = t >> 3;                   // 0..31
    const int p   = p0 + 4 * p4;
    const int crow = c0 + 8 * cr8;

    float4 r[8];
    if (p + 3 < RP_P) {
        #pragma unroll
        for (int j = 0; j < 8; ++j)
            r[j] = __ldg((const float4*)(feat +
                       ((size_t)(b * RP_C + crow + j)) * RP_P + p));
    } else {
        #pragma unroll
        for (int j = 0; j < 8; ++j) {
            float v[4];
            #pragma unroll
            for (int i = 0; i < 4; ++i)
                v[i] = (p + i < RP_P)
                     ? __ldg(feat + ((size_t)(b * RP_C + crow + j)) * RP_P + p + i)
                     : 0.f;
            r[j] = make_float4(v[0], v[1], v[2], v[3]);
        }
    }

    // position p+i gets channels crow..crow+7 packed as uint4 of half2;
    // 8-lane octets (same p, cr8=0..7) form contiguous 128B -> clean STG.128.
    #pragma unroll
    for (int i = 0; i < 4; ++i) {
        if (p + i < RP_P) {
            const uint4 o = make_uint4(
                pack2(sel4(r[0], i), sel4(r[1], i)),
                pack2(sel4(r[2], i), sel4(r[3], i)),
                pack2(sel4(r[4], i), sel4(r[5], i)),
                pack2(sel4(r[6], i), sel4(r[7], i)));
            g_featH4[(size_t)(b * RP_P + p + i) * PC8 + (c0 >> 3) + cr8] = o;
        }
    }
}

// ---------------- decode rois (1 block) ----------------
__global__ __launch_bounds__(256)
void decode_rois_kernel(const int* __restrict__ rois32)
{
    const int r = threadIdx.x;
    int odd = 0;                              // int64 => odd words all zero
    #pragma unroll
    for (int i = 0; i < 16; ++i) odd |= rois32[2 * i + 1];

    int b, x1, y1, x2, y2;
    if (odd == 0) {
        const int* rp = rois32 + r * 10;
        b = rp[0]; x1 = rp[2] >> 4; y1 = rp[4] >> 4; x2 = rp[6] >> 4; y2 = rp[8] >> 4;
    } else {
        const int* rp = rois32 + r * 5;
        b = rp[0]; x1 = rp[1] >> 4; y1 = rp[2] >> 4; x2 = rp[3] >> 4; y2 = rp[4] >> 4;
    }
    int* o = g_roi + r * 8;
    o[0] = b; o[1] = x1; o[2] = y1; o[3] = x2 - x1 + 1; o[4] = y2 - y1 + 1;
}

// ---------------- pool: block=(r,ph), 224 thr = 7 warps ----------------
#define SBS 264   // sbuf row stride (floats)

__global__ __launch_bounds__(224)
void roipool8_kernel(float* __restrict__ out)
{
    __shared__ float sbuf[RP_PW * SBS];

    const int r    = blockIdx.x;
    const int ph   = blockIdx.y;
    const int t    = threadIdx.x;
    const int pw   = t >> 5;                  // warp id = pw (uniform bw)
    const int lane = t & 31;                  // 8 channels: 8*lane..+7

    const int4 rb = *(const int4*)(g_roi + r * 8);   // b,x1,y1,w
    const int  h  = g_roi[r * 8 + 4];
    const int  b = rb.x, x1 = rb.y, y1 = rb.z, w = rb.w;

    const int sh = y1 + (ph * h) / RP_PH;
    const int eh = y1 + (((ph + 1) * h + (RP_PH - 1)) / RP_PH);
    const int nh = eh - sh;                   // 1..8

    const int sw = x1 + (pw * w) / RP_PW;
    const int ew = x1 + (((pw + 1) * w + (RP_PW - 1)) / RP_PW);
    const int bw = ew - sw;                   // 1..8, warp-uniform

    const uint4* __restrict__ q =
        g_featH4 + (size_t)(b * RP_P + sh * RP_W + sw) * PC8 + lane;

    uint4 acc = make_uint4(0xFC00FC00u, 0xFC00FC00u, 0xFC00FC00u, 0xFC00FC00u);

    if (bw == 1) {
        int y = 0;
        for (; y + 3 < nh; y += 4) {
            uint4 v0 = __ldg(q);
            uint4 v1 = __ldg(q + PRS);
            uint4 v2 = __ldg(q + 2 * PRS);
            uint4 v3 = __ldg(q + 3 * PRS);
            acc = h4max(acc, h4max(h4max(v0, v1), h4max(v2, v3)));
            q += 4 * PRS;
        }
        for (; y < nh; ++y) { acc = h4max(acc, __ldg(q)); q += PRS; }
    } else if (bw == 2) {
        int y = 0;
        for (; y + 1 < nh; y += 2) {
            uint4 v0 = __ldg(q);
            uint4 v1 = __ldg(q + PC8);
            uint4 v2 = __ldg(q + PRS);
            uint4 v3 = __ldg(q + PRS + PC8);
            acc = h4max(acc, h4max(h4max(v0, v1), h4max(v2, v3)));
            q += 2 * PRS;
        }
        if (y < nh) acc = h4max(acc, h4max(__ldg(q), __ldg(q + PC8)));
    } else {
        const int o3 = min(3, bw - 1) * PC8;  // dup when bw==3 (idempotent)
        int y = 0;
        for (; y + 1 < nh; y += 2) {
            uint4 v0 = __ldg(q);
            uint4 v1 = __ldg(q + PC8);
            uint4 v2 = __ldg(q + 2 * PC8);
            uint4 v3 = __ldg(q + o3);
            uint4 u0 = __ldg(q + PRS);
            uint4 u1 = __ldg(q + PRS + PC8);
            uint4 u2 = __ldg(q + PRS + 2 * PC8);
            uint4 u3 = __ldg(q + PRS + o3);
            for (int x = 4; x < bw; ++x) {    // rare, warp-uniform
                v1 = h4max(v1, __ldg(q + x * PC8));
                u1 = h4max(u1, __ldg(q + PRS + x * PC8));
            }
            v0 = h4max(h4max(v0, v1), h4max(v2, v3));
            u0 = h4max(h4max(u0, u1), h4max(u2, u3));
            acc = h4max(acc, h4max(v0, u0));
            q += 2 * PRS;
        }
        if (y < nh) {
            uint4 v0 = __ldg(q);
            uint4 v1 = __ldg(q + PC8);
            uint4 v2 = __ldg(q + 2 * PC8);
            uint4 v3 = __ldg(q + o3);
            for (int x = 4; x < bw; ++x)
                v1 = h4max(v1, __ldg(q + x * PC8));
            acc = h4max(acc, h4max(h4max(v0, v1), h4max(v2, v3)));
        }
    }

    // convert 8 halves -> fp32, stage
    {
        float* s = &sbuf[pw * SBS + 8 * lane];
        const float2 f0 = __half22float2(*(__half2*)&acc.x);
        const float2 f1 = __half22float2(*(__half2*)&acc.y);
        const float2 f2 = __half22float2(*(__half2*)&acc.z);
        const float2 f3 = __half22float2(*(__half2*)&acc.w);
        *(float4*)(s)     = make_float4(f0.x, f0.y, f1.x, f1.y);
        *(float4*)(s + 4) = make_float4(f2.x, f2.y, f3.x, f3.y);
    }
    __syncthreads();

    // write-out: 1792 floats, interleaved so stores merge within 28B chunks
    float* __restrict__ ob =
        out + (size_t)(r * RP_C) * (RP_PH * RP_PW) + ph * RP_PW;
    #pragma unroll
    for (int k = 0; k < 8; ++k) {
        const int idx = k * 224 + t;          // 0..1791
        const int c  = idx / 7;
        const int pp = idx % 7;
        ob[c * (RP_PH * RP_PW) + pp] = sbuf[pp * SBS + c];
    }
}

extern "C" void kernel_launch(void* const* d_in, const int* in_sizes, int n_in,
                              void* d_out, int out_size)
{
    const float* feat   = (const float*)d_in[0];
    const int*   rois32 = (const int*)d_in[1];
    float*       out    = (float*)d_out;

    dim3 tgrid((RP_P + 127) / 128, RP_C / 64, RP_B);   // 20 x 4 x 4
    transpose_kernel<<<tgrid, 256>>>(feat);

    decode_rois_kernel<<<1, 256>>>(rois32);

    dim3 pgrid(RP_R, RP_PH);                            // 256 x 7
    roipool8_kernel<<<pgrid, 224>>>(out);
}